// round 16
// baseline (speedup 1.0000x reference)
#include <cuda_runtime.h>
#include <cuda_fp16.h>
#include <cstdint>

#define NB 8
#define NC 64
#define NH 256
#define NW 512
#define NK 9
#define HW (NH * NW)                // 131,072
#define BHW (NB * NH * NW)          // 1,048,576

typedef unsigned long long ull;

// Scratch: P[k][b][y][x] = sum_c W[c,k] * F[b,c,y,x]   (fp16: 18.9 MB, L2-resident)
__device__ __half g_P[(size_t)NK * BHW];

// Packed f32x2 FMA (sm_100+): d = a*b + c on two lanes at once.
#define FMA_F32X2(d, a, b, c) \
    asm("fma.rn.f32x2 %0, %1, %2, %3;" : "=l"(d) : "l"(a), "l"(b), "l"(c))

// Wait for mbarrier phase (try_wait parity loop).
__device__ __forceinline__ void mbar_wait(uint32_t mbar, uint32_t phase) {
    uint32_t done = 0;
    while (!done) {
        asm volatile(
            "{\n\t.reg .pred p;\n\t"
            "mbarrier.try_wait.parity.shared.b64 p, [%1], %2;\n\t"
            "selp.b32 %0, 1, 0, p;\n\t}"
            : "=r"(done) : "r"(mbar), "r"(phase) : "memory");
    }
}

// ---------------------------------------------------------------------------
// Pass 1: channel reduction, TMA-bulk pipelined, feature stream EVICT-FIRST.
// (R15 config: validated best.) One block per (b,y) row. 64 channels in 8
// chunks of 8; 4-stage smem ring (16 KB/stage). Each chunk = 8 x
// cp.async.bulk 2KB with L2::evict_first so the 256 MB zero-reuse feature
// stream does not evict the P planes pass2 rereads.
// ---------------------------------------------------------------------------
__global__ void __launch_bounds__(256) pass1_kernel(
    const float* __restrict__ feature,   // [B, C, H, W]
    const float* __restrict__ weight)    // [1, C, 3, 3] -> [C, 9]
{
    extern __shared__ float buf[];       // [4 stages][8 ch][512 x] = 65536 B
    __shared__ float4 sw4[NK][NC / 2];   // {w_c,w_c,w_c1,w_c1} per (k, pair)
    __shared__ ull mbar[4];              // one full-barrier per stage

    const int t = threadIdx.x;

    for (int i = t; i < NK * (NC / 2); i += 256) {
        int k  = i % NK;
        int cc = i / NK;
        float w0 = weight[(2 * cc + 0) * NK + k];
        float w1 = weight[(2 * cc + 1) * NK + k];
        sw4[k][cc] = make_float4(w0, w0, w1, w1);
    }

    const uint32_t sbase = (uint32_t)__cvta_generic_to_shared(buf);
    const uint32_t mbase = (uint32_t)__cvta_generic_to_shared(mbar);

    ull pol;
    asm volatile("createpolicy.fractional.L2::evict_first.b64 %0, 1.0;"
                 : "=l"(pol));

    if (t == 0) {
#pragma unroll
        for (int s = 0; s < 4; ++s)
            asm volatile("mbarrier.init.shared.b64 [%0], 1;"
                         :: "r"(mbase + s * 8) : "memory");
    }
    __syncthreads();                     // publish mbarriers + sw4

    const int yb = blockIdx.x;           // b*NH + y
    const float* frow = feature
        + (size_t)(yb / NH) * NC * HW + (size_t)(yb % NH) * NW;

    // Fill stage s with chunk: thread 0 arms expect_tx then issues 8 x 2KB
    // bulk copies (one per channel row) with evict-first policy.
#define FILL(s, chunk)                                                        \
    do {                                                                      \
        if (t == 0) {                                                         \
            uint32_t mb = mbase + (s) * 8;                                    \
            asm volatile(                                                     \
                "mbarrier.arrive.expect_tx.shared.b64 _, [%0], %1;"           \
                :: "r"(mb), "r"(16384) : "memory");                           \
            const float* src0 = frow + (size_t)((chunk) * 8) * HW;            \
            _Pragma("unroll")                                                 \
            for (int c = 0; c < 8; ++c) {                                     \
                asm volatile(                                                 \
                    "cp.async.bulk.shared::cta.global"                        \
                    ".mbarrier::complete_tx::bytes.L2::cache_hint"            \
                    " [%0], [%1], %2, [%3], %4;"                              \
                    :: "r"(sbase + (uint32_t)((s) * 16384 + c * 2048)),       \
                       "l"(src0 + (size_t)c * HW), "r"(2048), "r"(mb),        \
                       "l"(pol)                                               \
                    : "memory");                                              \
            }                                                                 \
        }                                                                     \
    } while (0)

    ull acc[NK];
#pragma unroll
    for (int k = 0; k < NK; ++k) acc[k] = 0ull;

    // Prologue: 3 stages in flight.
    FILL(0, 0);
    FILL(1, 1);
    FILL(2, 2);

#pragma unroll
    for (int chunk = 0; chunk < 8; ++chunk) {
        // Wait for this chunk's stage (phase 0 for chunks 0-3, 1 for 4-7).
        mbar_wait(mbase + (chunk & 3) * 8, (chunk >> 2) & 1);

        const float* st = buf + (chunk & 3) * 4096;
#pragma unroll
        for (int p = 0; p < 4; ++p) {    // channel pairs within chunk
            ull f0 = *(const ull*)(st + (2 * p + 0) * 512 + 2 * t);
            ull f1 = *(const ull*)(st + (2 * p + 1) * 512 + 2 * t);
            int cidx = chunk * 4 + p;    // global pair index 0..31
#pragma unroll
            for (int k = 0; k < NK; ++k) {
                ulonglong2 wp = *(const ulonglong2*)&sw4[k][cidx];
                FMA_F32X2(acc[k], f0, wp.x, acc[k]);
                FMA_F32X2(acc[k], f1, wp.y, acc[k]);
            }
        }
        __syncthreads();                 // all consumers done before refill
        if (chunk + 3 < 8) FILL((chunk + 3) & 3, chunk + 3);
    }
#undef FILL

    // Store: thread owns x = {2t, 2t+1}; one 4B half2 store per tap.
    size_t pbase = (size_t)yb * NW + 2 * t;
#pragma unroll
    for (int k = 0; k < NK; ++k) {
        float2 v = *(float2*)&acc[k];
        __half2 h = __floats2half2_rn(v.x, v.y);
        *(__half2*)(g_P + (size_t)k * BHW + pbase) = h;
    }
}

// ---------------------------------------------------------------------------
// Pass 2: shift-identity gather + 2x2 upsample, occupancy-optimized.
// gi[h,w,k] = gi[h,0,k], gj[h,w,k] = (w + gj[h,0,k]) & 511 (validated).
// One thread per (h,w) x 2 batches; grid.y=4 covers 8 batches. Per-row
// 18 index ints are warp-broadcast L1 hits, so batch-splitting duplicates
// almost nothing. ~32 regs -> 6+ blocks/SM resident, 2x the warps of R15.
// ---------------------------------------------------------------------------
__global__ void __launch_bounds__(256) pass2_kernel(
    const int* __restrict__ gi,    // [H, W, 9]
    const int* __restrict__ gj,    // [H, W, 9]
    float* __restrict__ out)       // [B, 1, 2H, 2W]
{
    int g = blockIdx.x * 256 + threadIdx.x;      // [0, H*W)
    int h = g >> 9;
    int w = g & (NW - 1);
    int b0 = blockIdx.y * 2;                      // batch pair: 0,2,4,6

    const int* ri = gi + (size_t)h * NW * NK;     // row h, w=0
    const int* rj = gj + (size_t)h * NW * NK;

    int ys[NK], xs[NK];
#pragma unroll
    for (int k = 0; k < NK; ++k) ys[k] = ri[k];
#pragma unroll
    for (int k = 0; k < NK; ++k) xs[k] = (w + rj[k]) & (NW - 1);

    // Stage all 18 gathers (independent loads -> deep MLP).
    unsigned short v[NK][2];
#pragma unroll
    for (int k = 0; k < NK; ++k) {
        const unsigned short* Pk = (const unsigned short*)g_P + (size_t)k * BHW
                                 + ((size_t)b0 * NH + ys[k]) * NW + xs[k];
        v[k][0] = Pk[0];
        v[k][1] = Pk[HW];
    }

    float acc0 = 0.f, acc1 = 0.f;
#pragma unroll
    for (int k = 0; k < NK; ++k) {
        acc0 += __half2float(__ushort_as_half(v[k][0]));
        acc1 += __half2float(__ushort_as_half(v[k][1]));
    }

    // out viewed as float2: [B][2H][NW]; evict-first stores (no reuse).
    float2* o2 = (float2*)out;
    {
        size_t row0 = ((size_t)b0 * (2 * NH) + 2 * h) * NW + w;
        asm volatile("st.global.cs.v2.f32 [%0], {%1, %2};"
                     :: "l"(o2 + row0), "f"(acc0), "f"(acc0));
        asm volatile("st.global.cs.v2.f32 [%0], {%1, %2};"
                     :: "l"(o2 + row0 + NW), "f"(acc0), "f"(acc0));
        size_t row1 = ((size_t)(b0 + 1) * (2 * NH) + 2 * h) * NW + w;
        asm volatile("st.global.cs.v2.f32 [%0], {%1, %2};"
                     :: "l"(o2 + row1), "f"(acc1), "f"(acc1));
        asm volatile("st.global.cs.v2.f32 [%0], {%1, %2};"
                     :: "l"(o2 + row1 + NW), "f"(acc1), "f"(acc1));
    }
}

// ---------------------------------------------------------------------------
// Launch: graph-capturable, allocation-free.
// Inputs (metadata order): feature f32, weight f32, gi i32, gj i32.
// ---------------------------------------------------------------------------
extern "C" void kernel_launch(void* const* d_in, const int* in_sizes, int n_in,
                              void* d_out, int out_size)
{
    const float* feature = (const float*)d_in[0];
    const float* weight  = (const float*)d_in[1];
    const int*   gi      = (const int*)d_in[2];
    const int*   gj      = (const int*)d_in[3];
    float*       out     = (float*)d_out;

    // 64 KB dynamic smem opt-in (idempotent host call).
    static bool attr_set = false;
    if (!attr_set) {
        cudaFuncSetAttribute(pass1_kernel,
                             cudaFuncAttributeMaxDynamicSharedMemorySize, 65536);
        attr_set = true;
    }

    // Pass 1: one block per (b,y) row: 2048 blocks x 256 threads, 64KB smem
    pass1_kernel<<<NB * NH, 256, 65536>>>(feature, weight);
    // Pass 2: thread per (h,w) x 2 batches; grid (512, 4) x 256
    dim3 g2(NH * NW / 256, 4);
    pass2_kernel<<<g2, 256>>>(gi, gj, out);
}

// round 17
// speedup vs baseline: 1.5170x; 1.5170x over previous
#include <cuda_runtime.h>
#include <cuda_fp16.h>
#include <cstdint>

#define NB 8
#define NC 64
#define NH 256
#define NW 512
#define NK 9
#define HW (NH * NW)                // 131,072
#define BHW (NB * NH * NW)          // 1,048,576

typedef unsigned long long ull;

// Scratch: P[k][b][y][x] = sum_c W[c,k] * F[b,c,y,x]   (fp16: 18.9 MB, L2-resident)
__device__ __half g_P[(size_t)NK * BHW];

// Packed f32x2 FMA (sm_100+): d = a*b + c on two lanes at once.
#define FMA_F32X2(d, a, b, c) \
    asm("fma.rn.f32x2 %0, %1, %2, %3;" : "=l"(d) : "l"(a), "l"(b), "l"(c))

// Wait for mbarrier phase (try_wait parity loop).
__device__ __forceinline__ void mbar_wait(uint32_t mbar, uint32_t phase) {
    uint32_t done = 0;
    while (!done) {
        asm volatile(
            "{\n\t.reg .pred p;\n\t"
            "mbarrier.try_wait.parity.shared.b64 p, [%1], %2;\n\t"
            "selp.b32 %0, 1, 0, p;\n\t}"
            : "=r"(done) : "r"(mbar), "r"(phase) : "memory");
    }
}

// ---------------------------------------------------------------------------
// Pass 1: channel reduction, TMA-bulk pipelined, feature stream EVICT-FIRST.
// (R15 config: validated best.) One block per (b,y) row. 64 channels in 8
// chunks of 8; 4-stage smem ring (16 KB/stage). Each chunk = 8 x
// cp.async.bulk 2KB with L2::evict_first so the 256 MB zero-reuse feature
// stream does not evict the P planes pass2 rereads.
// ---------------------------------------------------------------------------
__global__ void __launch_bounds__(256) pass1_kernel(
    const float* __restrict__ feature,   // [B, C, H, W]
    const float* __restrict__ weight)    // [1, C, 3, 3] -> [C, 9]
{
    extern __shared__ float buf[];       // [4 stages][8 ch][512 x] = 65536 B
    __shared__ float4 sw4[NK][NC / 2];   // {w_c,w_c,w_c1,w_c1} per (k, pair)
    __shared__ ull mbar[4];              // one full-barrier per stage

    const int t = threadIdx.x;

    for (int i = t; i < NK * (NC / 2); i += 256) {
        int k  = i % NK;
        int cc = i / NK;
        float w0 = weight[(2 * cc + 0) * NK + k];
        float w1 = weight[(2 * cc + 1) * NK + k];
        sw4[k][cc] = make_float4(w0, w0, w1, w1);
    }

    const uint32_t sbase = (uint32_t)__cvta_generic_to_shared(buf);
    const uint32_t mbase = (uint32_t)__cvta_generic_to_shared(mbar);

    ull pol;
    asm volatile("createpolicy.fractional.L2::evict_first.b64 %0, 1.0;"
                 : "=l"(pol));

    if (t == 0) {
#pragma unroll
        for (int s = 0; s < 4; ++s)
            asm volatile("mbarrier.init.shared.b64 [%0], 1;"
                         :: "r"(mbase + s * 8) : "memory");
    }
    __syncthreads();                     // publish mbarriers + sw4

    const int yb = blockIdx.x;           // b*NH + y
    const float* frow = feature
        + (size_t)(yb / NH) * NC * HW + (size_t)(yb % NH) * NW;

    // Fill stage s with chunk: thread 0 arms expect_tx then issues 8 x 2KB
    // bulk copies (one per channel row) with evict-first policy.
#define FILL(s, chunk)                                                        \
    do {                                                                      \
        if (t == 0) {                                                         \
            uint32_t mb = mbase + (s) * 8;                                    \
            asm volatile(                                                     \
                "mbarrier.arrive.expect_tx.shared.b64 _, [%0], %1;"           \
                :: "r"(mb), "r"(16384) : "memory");                           \
            const float* src0 = frow + (size_t)((chunk) * 8) * HW;            \
            _Pragma("unroll")                                                 \
            for (int c = 0; c < 8; ++c) {                                     \
                asm volatile(                                                 \
                    "cp.async.bulk.shared::cta.global"                        \
                    ".mbarrier::complete_tx::bytes.L2::cache_hint"            \
                    " [%0], [%1], %2, [%3], %4;"                              \
                    :: "r"(sbase + (uint32_t)((s) * 16384 + c * 2048)),       \
                       "l"(src0 + (size_t)c * HW), "r"(2048), "r"(mb),        \
                       "l"(pol)                                               \
                    : "memory");                                              \
            }                                                                 \
        }                                                                     \
    } while (0)

    ull acc[NK];
#pragma unroll
    for (int k = 0; k < NK; ++k) acc[k] = 0ull;

    // Prologue: 3 stages in flight.
    FILL(0, 0);
    FILL(1, 1);
    FILL(2, 2);

#pragma unroll
    for (int chunk = 0; chunk < 8; ++chunk) {
        // Wait for this chunk's stage (phase 0 for chunks 0-3, 1 for 4-7).
        mbar_wait(mbase + (chunk & 3) * 8, (chunk >> 2) & 1);

        const float* st = buf + (chunk & 3) * 4096;
#pragma unroll
        for (int p = 0; p < 4; ++p) {    // channel pairs within chunk
            ull f0 = *(const ull*)(st + (2 * p + 0) * 512 + 2 * t);
            ull f1 = *(const ull*)(st + (2 * p + 1) * 512 + 2 * t);
            int cidx = chunk * 4 + p;    // global pair index 0..31
#pragma unroll
            for (int k = 0; k < NK; ++k) {
                ulonglong2 wp = *(const ulonglong2*)&sw4[k][cidx];
                FMA_F32X2(acc[k], f0, wp.x, acc[k]);
                FMA_F32X2(acc[k], f1, wp.y, acc[k]);
            }
        }
        __syncthreads();                 // all consumers done before refill
        if (chunk + 3 < 8) FILL((chunk + 3) & 3, chunk + 3);
    }
#undef FILL

    // Store: thread owns x = {2t, 2t+1}; one 4B half2 store per tap.
    size_t pbase = (size_t)yb * NW + 2 * t;
#pragma unroll
    for (int k = 0; k < NK; ++k) {
        float2 v = *(float2*)&acc[k];
        __half2 h = __floats2half2_rn(v.x, v.y);
        *(__half2*)(g_P + (size_t)k * BHW + pbase) = h;
    }
}

// ---------------------------------------------------------------------------
// Pass 2 (R15 config: validated best). Shift-identity indices:
// gi[h,w,k] = gi[h,0,k], gj[h,w,k] = (w + gj[h,0,k]) & 511.
// One thread per (h,w) x 4 batches; grid.y=2. The 18 per-row index ints are
// warp-broadcast L1 hits. All 36 fp16 gathers staged in registers for deep
// MLP; 4-batch amortization balances issue overhead vs occupancy (measured
// optimum over 2/4/8-batch splits). Output evict-first (no reuse).
// ---------------------------------------------------------------------------
__global__ void __launch_bounds__(256, 2) pass2_kernel(
    const int* __restrict__ gi,    // [H, W, 9]
    const int* __restrict__ gj,    // [H, W, 9]
    float* __restrict__ out)       // [B, 1, 2H, 2W]
{
    int g = blockIdx.x * 256 + threadIdx.x;      // [0, H*W)
    int h = g >> 9;
    int w = g & (NW - 1);
    int b0 = blockIdx.y * 4;                      // batch group: 0 or 4

    const int* ri = gi + (size_t)h * NW * NK;     // row h, w=0
    const int* rj = gj + (size_t)h * NW * NK;

    int ys[NK], xs[NK];
#pragma unroll
    for (int k = 0; k < NK; ++k) ys[k] = ri[k];
#pragma unroll
    for (int k = 0; k < NK; ++k) xs[k] = (w + rj[k]) & (NW - 1);

    // Stage all 36 gathers (independent loads -> deep MLP).
    unsigned short v[NK][4];
#pragma unroll
    for (int k = 0; k < NK; ++k) {
        const unsigned short* Pk = (const unsigned short*)g_P + (size_t)k * BHW
                                 + ((size_t)b0 * NH + ys[k]) * NW + xs[k];
#pragma unroll
        for (int j = 0; j < 4; ++j)
            v[k][j] = Pk[(size_t)j * HW];
    }

    float acc[4] = {0.f, 0.f, 0.f, 0.f};
#pragma unroll
    for (int k = 0; k < NK; ++k)
#pragma unroll
        for (int j = 0; j < 4; ++j)
            acc[j] += __half2float(__ushort_as_half(v[k][j]));

    // out viewed as float2: [B][2H][NW]; evict-first stores (no reuse).
    float2* o2 = (float2*)out;
#pragma unroll
    for (int j = 0; j < 4; ++j) {
        float2 val = make_float2(acc[j], acc[j]);
        size_t row0 = ((size_t)(b0 + j) * (2 * NH) + 2 * h) * NW + w;
        asm volatile("st.global.cs.v2.f32 [%0], {%1, %2};"
                     :: "l"(o2 + row0), "f"(val.x), "f"(val.y));
        asm volatile("st.global.cs.v2.f32 [%0], {%1, %2};"
                     :: "l"(o2 + row0 + NW), "f"(val.x), "f"(val.y));
    }
}

// ---------------------------------------------------------------------------
// Launch: graph-capturable, allocation-free.
// Inputs (metadata order): feature f32, weight f32, gi i32, gj i32.
// ---------------------------------------------------------------------------
extern "C" void kernel_launch(void* const* d_in, const int* in_sizes, int n_in,
                              void* d_out, int out_size)
{
    const float* feature = (const float*)d_in[0];
    const float* weight  = (const float*)d_in[1];
    const int*   gi      = (const int*)d_in[2];
    const int*   gj      = (const int*)d_in[3];
    float*       out     = (float*)d_out;

    // 64 KB dynamic smem opt-in (idempotent host call).
    static bool attr_set = false;
    if (!attr_set) {
        cudaFuncSetAttribute(pass1_kernel,
                             cudaFuncAttributeMaxDynamicSharedMemorySize, 65536);
        attr_set = true;
    }

    // Pass 1: one block per (b,y) row: 2048 blocks x 256 threads, 64KB smem
    pass1_kernel<<<NB * NH, 256, 65536>>>(feature, weight);
    // Pass 2: thread per (h,w) x 4 batches; grid (512, 2) x 256
    dim3 g2(NH * NW / 256, 2);
    pass2_kernel<<<g2, 256>>>(gi, gj, out);
}